// round 17
// baseline (speedup 1.0000x reference)
#include <cuda_runtime.h>
#include <math.h>
#include <stdint.h>

#define Bn 4
#define Dn 64
#define Hn 64
#define Wn 64
#define PLANE 4096
#define VOL   262144
#define VOX   1048576

typedef unsigned long long ull;

__device__ float g_p[VOX];
__device__ float g_c[VOX];   // r * (1 - p)
__device__ float g_v[VOX];   // ping-pong buffer

// ---------------- helpers ----------------
__device__ __forceinline__ float4 max4(float4 a, float4 b) {
    return make_float4(fmaxf(a.x, b.x), fmaxf(a.y, b.y),
                       fmaxf(a.z, b.z), fmaxf(a.w, b.w));
}
__device__ __forceinline__ uint32_t cvt_tf32(float x) {
    uint32_t r; asm("cvt.rna.tf32.f32 %0, %1;" : "=r"(r) : "f"(x)); return r;
}
// warp-level tf32 MMA (base ISA, compiles for sm_103)
__device__ __forceinline__ void mma_tf32(float& c0, float& c1, float& c2, float& c3,
                                         const uint32_t a[4], const uint32_t b[2]) {
    asm volatile(
        "mma.sync.aligned.m16n8k8.row.col.f32.tf32.tf32.f32 "
        "{%0,%1,%2,%3}, {%4,%5,%6,%7}, {%8,%9}, {%0,%1,%2,%3};"
        : "+f"(c0), "+f"(c1), "+f"(c2), "+f"(c3)
        : "r"(a[0]), "r"(a[1]), "r"(a[2]), "r"(a[3]), "r"(b[0]), "r"(b[1]));
}

// ---------------------------------------------------------------------------
// Kernel 1 (R15 winner): tf32 mma.sync implicit-GEMM conv, nt-outer.
// ---------------------------------------------------------------------------
#define XH  10
#define XRW 68
#define BSTR 17
#define NCH 152
#define NT  19

__global__ __launch_bounds__(256) void conv_mma_kernel(
    const float* __restrict__ image, const float* __restrict__ hw,
    const float* __restrict__ hb,    const float* __restrict__ pw,
    float* __restrict__ vout)
{
    __shared__ float  xs[3 * XH * XRW];
    __shared__ float2 B2[NCH * BSTR];
    __shared__ float2 wb[NCH];

    const int tid  = threadIdx.x;
    const int warp = tid >> 5;
    const int lane = tid & 31;
    const int d0 = blockIdx.x;
    const int h0 = blockIdx.y * 8;
    const int b  = blockIdx.z;

    for (int i = tid; i < NCH * 16; i += 256) {
        const int ch = i >> 4, kp = i & 15;
        const int kk = kp >> 2, j = kp & 3;
        const int t0 = kk * 8 + j, t1 = t0 + 4;
        const float w0 = (ch < 150 && t0 < 27) ? hw[ch * 27 + t0] : 0.f;
        const float w1 = (ch < 150 && t1 < 27) ? hw[ch * 27 + t1] : 0.f;
        B2[ch * BSTR + kp] = make_float2(__uint_as_float(cvt_tf32(w0)),
                                         __uint_as_float(cvt_tf32(w1)));
    }
    for (int i = tid; i < NCH; i += 256)
        wb[i] = (i < 150) ? make_float2(pw[i], hb[i]) : make_float2(0.f, 0.f);

    const float* xg = image + (size_t)b * 2 * VOL;
    const float* rg = xg + VOL;
    for (int i = tid; i < 3 * XH * 66; i += 256) {
        const int wl = i % 66; const int rest = i / 66;
        const int rl = rest % XH; const int dz = rest / XH;
        const int gw = wl - 1, gh = h0 + rl - 1, gd = d0 + dz - 1;
        float v = 0.f;
        if (gw >= 0 && gw < Wn && gh >= 0 && gh < Hn && gd >= 0 && gd < Dn)
            v = xg[((size_t)gd * Hn + gh) * Wn + gw];
        xs[(dz * XH + rl) * XRW + wl] = v;
    }
    __syncthreads();

    const int g   = lane >> 2;
    const int tig = lane & 3;
    const int hl  = warp;

    uint32_t afr[4][4][4];
    #pragma unroll
    for (int mt = 0; mt < 4; mt++)
        #pragma unroll
        for (int kk = 0; kk < 4; kk++)
            #pragma unroll
            for (int hh = 0; hh < 2; hh++) {
                const int t = kk * 8 + tig + hh * 4;
                uint32_t lo = 0u, hi = 0u;
                if (t < 27) {
                    const int dz = t / 9, rem = t - dz * 9;
                    const int hy = rem / 3, kx = rem - hy * 3;
                    const float* rp = &xs[(dz * XH + hl + hy) * XRW + mt * 16 + g + kx];
                    lo = cvt_tf32(rp[0]);
                    hi = cvt_tf32(rp[8]);
                }
                afr[mt][kk][hh * 2 + 0] = lo;
                afr[mt][kk][hh * 2 + 1] = hi;
            }

    float zz[4][2];
    #pragma unroll
    for (int mt = 0; mt < 4; mt++) { zz[mt][0] = 0.f; zz[mt][1] = 0.f; }

    #pragma unroll 1
    for (int nt = 0; nt < NT; nt++) {
        uint32_t bfr[4][2];
        const float2* bp = &B2[(nt * 8 + g) * BSTR + tig];
        #pragma unroll
        for (int kk = 0; kk < 4; kk++) {
            const float2 bb = bp[kk * 4];
            bfr[kk][0] = __float_as_uint(bb.x);
            bfr[kk][1] = __float_as_uint(bb.y);
        }
        const float4 wq = *(const float4*)&wb[nt * 8 + 2 * tig];

        #pragma unroll
        for (int mt = 0; mt < 4; mt++) {
            float c0 = 0.f, c1 = 0.f, c2 = 0.f, c3 = 0.f;
            #pragma unroll
            for (int kk = 0; kk < 4; kk++)
                mma_tf32(c0, c1, c2, c3, afr[mt][kk], bfr[kk]);

            zz[mt][0] = fmaf(wq.x, fmaxf(c0 + wq.y, 0.f),
                        fmaf(wq.z, fmaxf(c1 + wq.w, 0.f), zz[mt][0]));
            zz[mt][1] = fmaf(wq.x, fmaxf(c2 + wq.y, 0.f),
                        fmaf(wq.z, fmaxf(c3 + wq.w, 0.f), zz[mt][1]));
        }
    }

    #pragma unroll
    for (int mt = 0; mt < 4; mt++) {
        float z0 = zz[mt][0], z1 = zz[mt][1];
        z0 += __shfl_xor_sync(0xffffffffu, z0, 1);
        z0 += __shfl_xor_sync(0xffffffffu, z0, 2);
        z1 += __shfl_xor_sync(0xffffffffu, z1, 1);
        z1 += __shfl_xor_sync(0xffffffffu, z1, 2);

        if (tig < 2) {
            const int w  = mt * 16 + g + (tig == 1 ? 8 : 0);
            const float z = (tig == 1) ? z1 : z0;
            const int gh = h0 + hl;
            const size_t o = ((size_t)b * Dn + d0) * PLANE + gh * Wn + w;
            const float r = rg[((size_t)d0 * Hn + gh) * Wn + w];
            const float p = 1.f / (1.f + __expf(-z));
            g_p[o]  = p;
            g_c[o]  = r * (1.f - p);
            vout[o] = r;
        }
    }
}

// ---------------------------------------------------------------------------
// Kernel 2: TWO fused iterations, 2 barriers.
// Block = 32-row half-plane of (b,d); 512 blocks.
// Stage A: v0 d-max for planes d-1..d+1 into 3 smem buffers (36 rows each).
// Stage B: v1 for the 3 planes via shuffled w-max; max-accumulate into m1
//          (same-thread mapping across planes -> no barrier); stash v1 center.
// Stage C: h/w-max over m1 (= v2 d-max) + update + store.
// Clamped-index duplication is exact for max-pooling.
// ---------------------------------------------------------------------------
__global__ __launch_bounds__(256) void iter2_kernel(
    const float4* __restrict__ vin, float4* __restrict__ vout,
    const int* __restrict__ kptr, int it)
{
    __shared__ float4 zbuf[3][36][16];   // 27648 B
    __shared__ float4 m1[34][16];        //  8704 B
    __shared__ float4 v1c[32][16];       //  8192 B

    const int blk = blockIdx.x;
    const int bd  = blk >> 1;
    const int b   = bd >> 6;
    const int d   = bd & 63;
    const int h0  = (blk & 1) * 32;
    const int tid = threadIdx.x;
    const int lane = tid & 31;
    const int ks  = *kptr;

    const size_t bb = (size_t)b * 64 * 1024;
    const float4* Gp = (const float4*)g_p;
    const float4* Gc = (const float4*)g_c;

    // ---- stage A: d-max of v0 for v1 planes pd_i = clamp(d-1+i) ----
    #pragma unroll
    for (int q = 0; q < 7; q++) {
        const int j = tid + q * 256;
        if (j < 3 * 36 * 16) {
            const int c4 = j & 15; const int rest = j >> 4;
            const int row = rest % 36; const int i = rest / 36;
            const int pd = min(63, max(0, d - 1 + i));
            const int q0 = max(0, pd - 1), q2 = min(63, pd + 1);
            const int gh = min(63, max(0, h0 - 2 + row));
            const size_t ro = (size_t)gh * 16 + c4;
            float4 m = vin[bb + (size_t)pd * 1024 + ro];
            m = max4(m, vin[bb + (size_t)q0 * 1024 + ro]);
            m = max4(m, vin[bb + (size_t)q2 * 1024 + ro]);
            zbuf[i][row][c4] = m;
        }
    }
    __syncthreads();

    // ---- stage B: v1 on 3 planes; accumulate m1; stash center plane ----
    #pragma unroll 1
    for (int i = 0; i < 3; i++) {
        const int pd = min(63, max(0, d - 1 + i));
        const size_t pbase = bb + (size_t)pd * 1024;

        #pragma unroll
        for (int chunk = 0; chunk < 3; chunk++) {
            int rv, c4;
            bool act = true;
            if (chunk < 2) { rv = chunk * 16 + (tid >> 4); c4 = tid & 15; }
            else { act = (tid < 32); rv = 32 + (tid >> 4); c4 = tid & 15; }
            if (!act) continue;

            float4 hm = max4(max4(zbuf[i][rv][c4], zbuf[i][rv + 1][c4]),
                             zbuf[i][rv + 2][c4]);

            float lf = __shfl_up_sync(0xffffffffu, hm.w, 1);
            float rt = __shfl_down_sync(0xffffffffu, hm.x, 1);
            if (c4 == 0)  lf = hm.x;
            if (c4 == 15) rt = hm.w;

            float4 m;
            m.x = fmaxf(lf,   fmaxf(hm.x, hm.y));
            m.y = fmaxf(hm.x, fmaxf(hm.y, hm.z));
            m.z = fmaxf(hm.y, fmaxf(hm.z, hm.w));
            m.w = fmaxf(hm.z, fmaxf(hm.w, rt));

            const int gh = min(63, max(0, h0 - 1 + rv));
            const size_t off = pbase + (size_t)gh * 16 + c4;
            const float4 v0c = vin[off];
            const float4 pp  = Gp[off];
            const float4 cc  = Gc[off];

            float4 v1;
            v1.x = fmaxf(v0c.x, fmaf(pp.x, m.x, cc.x));
            v1.y = fmaxf(v0c.y, fmaf(pp.y, m.y, cc.y));
            v1.z = fmaxf(v0c.z, fmaf(pp.z, m.z, cc.z));
            v1.w = fmaxf(v0c.w, fmaf(pp.w, m.w, cc.w));
            if (ks <= it) v1 = v0c;            // iteration 'it' disabled

            m1[rv][c4] = (i == 0) ? v1 : max4(m1[rv][c4], v1);
            if (i == 1 && rv >= 1 && rv <= 32) v1c[rv - 1][c4] = v1;
        }
    }
    __syncthreads();

    // ---- stage C: v2 = max(v1, p * hwmax(m1) + c) ----
    #pragma unroll
    for (int chunk = 0; chunk < 2; chunk++) {
        const int ro = chunk * 16 + (tid >> 4);
        const int c4 = tid & 15;

        float4 hm = max4(max4(m1[ro][c4], m1[ro + 1][c4]), m1[ro + 2][c4]);

        float lf = __shfl_up_sync(0xffffffffu, hm.w, 1);
        float rt = __shfl_down_sync(0xffffffffu, hm.x, 1);
        if (c4 == 0)  lf = hm.x;
        if (c4 == 15) rt = hm.w;

        float4 m;
        m.x = fmaxf(lf,   fmaxf(hm.x, hm.y));
        m.y = fmaxf(hm.x, fmaxf(hm.y, hm.z));
        m.z = fmaxf(hm.y, fmaxf(hm.z, hm.w));
        m.w = fmaxf(hm.z, fmaxf(hm.w, rt));

        const size_t off = bb + (size_t)d * 1024 + (size_t)(h0 + ro) * 16 + c4;
        const float4 v1cen = v1c[ro][c4];
        const float4 pp = Gp[off];
        const float4 cc = Gc[off];

        float4 v2;
        v2.x = fmaxf(v1cen.x, fmaf(pp.x, m.x, cc.x));
        v2.y = fmaxf(v1cen.y, fmaf(pp.y, m.y, cc.y));
        v2.z = fmaxf(v1cen.z, fmaf(pp.z, m.z, cc.z));
        v2.w = fmaxf(v1cen.w, fmaf(pp.w, m.w, cc.w));
        if (ks <= it + 1) v2 = v1cen;          // iteration 'it+1' disabled

        vout[off] = v2;
    }
}

// ---------------------------------------------------------------------------
extern "C" void kernel_launch(void* const* d_in, const int* in_sizes, int n_in,
                              void* d_out, int out_size)
{
    const float* image = (const float*)d_in[0];
    const float* hw    = (const float*)d_in[1];
    const float* hb    = (const float*)d_in[2];
    const float* pw    = (const float*)d_in[3];
    const int*   kptr  = (const int*)d_in[4];
    float* out = (float*)d_out;

    void* pv = nullptr;
    cudaGetSymbolAddress(&pv, g_v);
    float* vbuf = (float*)pv;

    // v0 -> vbuf; 15 fused launches alternate out/vbuf, ending in d_out.
    conv_mma_kernel<<<dim3(64, 8, 4), 256>>>(image, hw, hb, pw, vbuf);

    const float* src = vbuf;
    float* dst = out;
    for (int i = 0; i < 30; i += 2) {
        iter2_kernel<<<Bn * Dn * 2, 256>>>((const float4*)src, (float4*)dst, kptr, i);
        float* t = dst; dst = (float*)src; src = t;
    }
    // 15 launches (odd count) starting at dst=out: final write lands in d_out.
}